// round 16
// baseline (speedup 1.0000x reference)
#include <cuda_runtime.h>
#include <cuda_fp16.h>
#include <cstdint>

// ---------------- problem dims ----------------
#define B_   64
#define NIN  2048
#define H_   1024
#define NOUT 2
#define T_   128
#define M_   (B_ * T_)          // 8192 time-batched rows

__device__ __constant__ float CD = (float)(1.0 - 0.3);
__device__ __constant__ float VD = (float)(1.0 - 0.8);
#define THRESH 1.0f

// Quantization scales: s1 = 14*sigma/127 (sigma = 1/sqrt(K)); s2 = s1/254; s3 = s2/254.
// max|w| over ~2M N(0,sigma) samples ~ 5.4 sigma << 14 sigma -> clamp never triggers.
#define S1_L1 (0.30940108f / 127.0f)    // 14 / sqrt(2048) / 127
#define S1_L2 (0.43750000f / 127.0f)    // 14 / sqrt(1024) / 127

// ---------------- scratch ----------------
__device__ __align__(256) int8_t g_A1[(size_t)M_ * NIN];        // int8 spikes [M][NIN]
__device__ __align__(256) int8_t g_A2[(size_t)M_ * H_];         // int8 spikes [M][H]
__device__ __align__(256) int8_t g_W1q[(size_t)3 * H_ * NIN];   // int8 [sp][H][NIN]
__device__ __align__(256) int8_t g_W2q[(size_t)3 * H_ * H_];    // int8 [sp][H][H]
__device__ float g_Z [(size_t)M_ * H_];                         // fp32 pre-activation
__device__ float g_S2[(size_t)M_ * H_];                         // fp32 layer-2 spikes
__device__ float g_Z3[(size_t)M_ * NOUT];

// ---------------- PTX helpers (base ISA only) ----------------
__device__ __forceinline__ uint32_t smem_u32(const void* p) {
    uint32_t a;
    asm("{ .reg .u64 t; cvta.to.shared.u64 t, %1; cvt.u32.u64 %0, t; }" : "=r"(a) : "l"(p));
    return a;
}
__device__ __forceinline__ void cpasync16(uint32_t dst, const void* src) {
    asm volatile("cp.async.cg.shared.global [%0], [%1], 16;" :: "r"(dst), "l"(src));
}
#define CP_COMMIT() asm volatile("cp.async.commit_group;" ::: "memory")
#define CP_WAIT1()  asm volatile("cp.async.wait_group 1;" ::: "memory")

__device__ __forceinline__ void ldsm_x4(uint32_t (&r)[4], uint32_t addr) {
    asm volatile("ldmatrix.sync.aligned.m8n8.x4.shared.b16 {%0,%1,%2,%3}, [%4];"
        : "=r"(r[0]), "=r"(r[1]), "=r"(r[2]), "=r"(r[3]) : "r"(addr));
}
// int8 IMMA: D(s32) += A(s8,16x32) * B(s8,32x8)^T
__device__ __forceinline__ void imma16832(int32_t (&d)[4], const uint32_t (&a)[4],
                                          uint32_t b0, uint32_t b1) {
    asm volatile(
        "mma.sync.aligned.m16n8k32.row.col.s32.s8.s8.s32 "
        "{%0,%1,%2,%3}, {%4,%5,%6,%7}, {%8,%9}, {%0,%1,%2,%3};"
        : "+r"(d[0]), "+r"(d[1]), "+r"(d[2]), "+r"(d[3])
        : "r"(a[0]), "r"(a[1]), "r"(a[2]), "r"(a[3]), "r"(b0), "r"(b1));
}

// ---------------- 1) transpose: spike [B,I,T] -> A1 int8 [m=(t*B+b)][i] ----------------
__global__ void transpose_spike(const float* __restrict__ in, int8_t* __restrict__ a1) {
    __shared__ float tile[32][33];
    const int b  = blockIdx.z;
    const int i0 = blockIdx.y * 32;
    const int t0 = blockIdx.x * 32;
    const int tx = threadIdx.x, ty = threadIdx.y;   // 32 x 8
#pragma unroll
    for (int r = 0; r < 32; r += 8)
        tile[ty + r][tx] = in[((size_t)b * NIN + (i0 + ty + r)) * T_ + (t0 + tx)];
    __syncthreads();
#pragma unroll
    for (int r = 0; r < 32; r += 8) {
        const int t = t0 + ty + r;
        const int i = i0 + tx;
        const int m = t * B_ + b;
        a1[(size_t)m * NIN + i] = (tile[tx][ty + r] != 0.0f) ? (int8_t)1 : (int8_t)0;
    }
}

// ---------------- 2) weight 3-term int8 split (double-precision residuals) ----------------
__global__ void wsplit_i8(const float* __restrict__ W, int8_t* __restrict__ out, int K,
                          float s1f, float s2f, float s3f) {
    const int ng  = K / 16;
    const int idx = blockIdx.x * blockDim.x + threadIdx.x;
    if (idx >= H_ * ng) return;
    const int n = idx / ng, k0 = (idx % ng) * 16;
    const double s1 = (double)s1f, s2 = (double)s2f, s3 = (double)s3f;
    union { int8_t q[16]; uint4 v; } o1, o2, o3;
#pragma unroll
    for (int j = 0; j < 16; j++) {
        const double w = (double)W[(size_t)n * K + k0 + j];
        int q1 = __double2int_rn(w / s1);  q1 = max(-127, min(127, q1));
        const double r1 = w - s1 * q1;
        int q2 = __double2int_rn(r1 / s2); q2 = max(-127, min(127, q2));
        const double r2 = r1 - s2 * q2;
        int q3 = __double2int_rn(r2 / s3); q3 = max(-127, min(127, q3));
        o1.q[j] = (int8_t)q1; o2.q[j] = (int8_t)q2; o3.q[j] = (int8_t)q3;
    }
    const size_t sz = (size_t)H_ * K;
    *(uint4*)&out[(size_t)0 * sz + (size_t)n * K + k0] = o1.v;
    *(uint4*)&out[(size_t)1 * sz + (size_t)n * K + k0] = o2.v;
    *(uint4*)&out[(size_t)2 * sz + (size_t)n * K + k0] = o3.v;
}

// ---------------- 3) IMMA GEMM: C = s1*(A·q1) + s2*(A·q2) + s3*(A·q3), s32 exact ----------------
// CTA 128x64 tile, 512 threads, 16 warps (4m x 4n), warp tile 32x16.
// K-chunk 64 int8 (2 k32 steps), 2-stage cp.async.
#define ROWB 80                          // 64B data + 16B pad: ldmatrix conflict-free
#define ATILE (128 * ROWB)               // 10240
#define WTILE (64 * ROWB)                // 5120
#define STG_BYTES (ATILE + 3 * WTILE)    // 25600
#define GEMM_SMEM (2 * STG_BYTES)        // 51200

__device__ __forceinline__ void load_stage(uint32_t st, const int8_t* __restrict__ Ab,
                                           const int8_t* __restrict__ Wb,
                                           int bm, int bn, int c, int K, int tid) {
    const size_t koff = (size_t)c * 64;
    {   // A: 128 rows x 64B = 512 x 16B, one per thread
        const int row = tid >> 2, ch = tid & 3;
        cpasync16(st + row * ROWB + ch * 16,
                  Ab + (size_t)(bm + row) * K + koff + ch * 16);
    }
    if (tid < 256) {                     // W: 3 splits x 64 rows x 64B = 256 x 16B each
        const int row = tid >> 2, ch = tid & 3;
#pragma unroll
        for (int sp = 0; sp < 3; sp++)
            cpasync16(st + ATILE + sp * WTILE + row * ROWB + ch * 16,
                      Wb + ((size_t)sp * H_ + bn + row) * K + koff + ch * 16);
    }
}

__global__ __launch_bounds__(512, 1)
void imma_gemm(const int8_t* __restrict__ Ab, const int8_t* __restrict__ Wb,
               float* __restrict__ C, int K, float s1, float s2, float s3) {
    extern __shared__ uint8_t smem[];
    const uint32_t sb = smem_u32(smem);
    const int tid = threadIdx.x, lane = tid & 31, wid = tid >> 5;
    const int wm = wid >> 2, wn = wid & 3;     // 4 x 4 warp grid; warp tile 32m x 16n
    const int bm = blockIdx.y * 128, bn = blockIdx.x * 64;
    const int nch = K / 64;

    int32_t acc[3][2][2][4];                   // [split][m-tile][n-tile][4]
#pragma unroll
    for (int sp = 0; sp < 3; sp++)
#pragma unroll
        for (int i = 0; i < 2; i++)
#pragma unroll
            for (int j = 0; j < 2; j++)
#pragma unroll
                for (int v = 0; v < 4; v++) acc[sp][i][j][v] = 0;

    load_stage(sb,             Ab, Wb, bm, bn, 0, K, tid); CP_COMMIT();
    load_stage(sb + STG_BYTES, Ab, Wb, bm, bn, 1, K, tid); CP_COMMIT();

    const int r16  = lane & 15;
    const int hb16 = (lane >> 4) << 4;

    for (int c = 0; c < nch; c++) {
        CP_WAIT1();
        __syncthreads();
        const uint32_t stage = sb + (c & 1) * STG_BYTES;
#pragma unroll
        for (int s = 0; s < 2; s++) {          // 2 x k32 steps
            // B frags: 16 n-rows x 32B per split -> ldsm_x4
            // frag order: [0]=(n0-7,k0-15) [1]=(n8-15,k0-15) [2]=(n0-7,k16-31) [3]=(n8-15,k16-31)
            uint32_t b[3][4];
#pragma unroll
            for (int sp = 0; sp < 3; sp++)
                ldsm_x4(b[sp], stage + ATILE + sp * WTILE +
                               (wn * 16 + r16) * ROWB + s * 32 + hb16);
#pragma unroll
            for (int i = 0; i < 2; i++) {      // 2 m-tiles of 16 rows
                uint32_t a[4];
                ldsm_x4(a, stage + (wm * 32 + i * 16 + r16) * ROWB + s * 32 + hb16);
#pragma unroll
                for (int sp = 0; sp < 3; sp++) {
                    imma16832(acc[sp][i][0], a, b[sp][0], b[sp][2]);   // n-tile 0
                    imma16832(acc[sp][i][1], a, b[sp][1], b[sp][3]);   // n-tile 1
                }
            }
        }
        __syncthreads();
        if (c + 2 < nch) load_stage(stage, Ab, Wb, bm, bn, c + 2, K, tid);
        CP_COMMIT();
    }

    // epilogue: z = s1*Z1 + s2*Z2 + s3*Z3 (s32 -> f32 conversion exact)
    const int rr = lane >> 2, cc = (lane & 3) * 2;
#pragma unroll
    for (int i = 0; i < 2; i++) {
        const int row = bm + wm * 32 + i * 16 + rr;
#pragma unroll
        for (int nt = 0; nt < 2; nt++) {
            const int col = bn + wn * 16 + nt * 8 + cc;
            float v[4];
#pragma unroll
            for (int u = 0; u < 4; u++)
                v[u] = fmaf(s1, (float)acc[0][i][nt][u],
                       fmaf(s2, (float)acc[1][i][nt][u],
                            s3 * (float)acc[2][i][nt][u]));
            *(float2*)&C[(size_t)row * H_ + col]       = make_float2(v[0], v[1]);
            *(float2*)&C[(size_t)(row + 8) * H_ + col] = make_float2(v[2], v[3]);
        }
    }
}

// ---------------- 4) scans ----------------
__global__ void scan_i8(const float* __restrict__ Z, int8_t* __restrict__ a2) {
    const int n = blockIdx.x * blockDim.x + threadIdx.x;   // n = b*H + o
    if (n >= B_ * H_) return;
    const int b = n >> 10, o = n & 1023;
    float cur = 0.f, vol = 0.f;
    const float cd = CD, vd = VD;
    for (int t = 0; t < T_; t++) {
        const float z = Z[(size_t)t * (B_ * H_) + n];
        cur = cur * cd + z;
        vol = vol * vd + cur;
        const bool s = (vol - THRESH >= 0.f);
        vol = s ? 0.f : vol;
        a2[(size_t)(t * B_ + b) * H_ + o] = s ? (int8_t)1 : (int8_t)0;
    }
}

__global__ void scan_f32(const float* __restrict__ Z, float* __restrict__ S, int Nn) {
    const int n = blockIdx.x * blockDim.x + threadIdx.x;
    if (n >= Nn) return;
    float cur = 0.f, vol = 0.f;
    const float cd = CD, vd = VD;
#pragma unroll 4
    for (int t = 0; t < T_; t++) {
        const float z = Z[(size_t)t * Nn + n];
        cur = cur * cd + z;
        vol = vol * vd + cur;
        const float s = (vol - THRESH >= 0.f) ? 1.f : 0.f;
        vol = (s > 0.f) ? 0.f : vol;
        S[(size_t)t * Nn + n] = s;
    }
}

// ---------------- 5) layer-3 GEMM (N=2): one warp per row ----------------
__global__ void gemm3_kernel(const float* __restrict__ S2, const float* __restrict__ W3,
                             float* __restrict__ Z3) {
    const int warp = (blockIdx.x * blockDim.x + threadIdx.x) >> 5;
    const int lane = threadIdx.x & 31;
    if (warp >= M_) return;
    const float* s = S2 + (size_t)warp * H_;
    float a0 = 0.f, a1 = 0.f;
#pragma unroll 8
    for (int k = lane; k < H_; k += 32) {
        const float sv = s[k];
        a0 += sv * W3[k];
        a1 += sv * W3[H_ + k];
    }
#pragma unroll
    for (int off = 16; off; off >>= 1) {
        a0 += __shfl_xor_sync(0xFFFFFFFFu, a0, off);
        a1 += __shfl_xor_sync(0xFFFFFFFFu, a1, off);
    }
    if (lane == 0) { Z3[(size_t)warp * 2] = a0; Z3[(size_t)warp * 2 + 1] = a1; }
}

// ---------------- 6) layer-3 scan + final output [B, 2, T] ----------------
__global__ void scan3_kernel(const float* __restrict__ Z3, float* __restrict__ out) {
    const int n = threadIdx.x;
    const int b = n >> 1, o = n & 1;
    float cur = 0.f, vol = 0.f;
    const float cd = CD, vd = VD;
    for (int t = 0; t < T_; t++) {
        const float z = Z3[t * (B_ * NOUT) + n];
        cur = cur * cd + z;
        vol = vol * vd + cur;
        const float s = (vol - THRESH >= 0.f) ? 1.f : 0.f;
        vol = (s > 0.f) ? 0.f : vol;
        out[((size_t)b * NOUT + o) * T_ + t] = s;
    }
}

// ---------------- launch ----------------
extern "C" void kernel_launch(void* const* d_in, const int* in_sizes, int n_in,
                              void* d_out, int out_size) {
    const float* spike = (const float*)d_in[0];   // [B, NIN, T]
    const float* W1    = (const float*)d_in[1];   // [H, NIN]
    const float* W2    = (const float*)d_in[2];   // [H, H]
    const float* W3    = (const float*)d_in[3];   // [NOUT, H]
    float* out = (float*)d_out;

    int8_t *A1, *A2, *W1q, *W2q;
    float *Z, *S2, *Z3;
    cudaGetSymbolAddress((void**)&A1,  g_A1);
    cudaGetSymbolAddress((void**)&A2,  g_A2);
    cudaGetSymbolAddress((void**)&W1q, g_W1q);
    cudaGetSymbolAddress((void**)&W2q, g_W2q);
    cudaGetSymbolAddress((void**)&Z,   g_Z);
    cudaGetSymbolAddress((void**)&S2,  g_S2);
    cudaGetSymbolAddress((void**)&Z3,  g_Z3);

    cudaFuncSetAttribute(imma_gemm, cudaFuncAttributeMaxDynamicSharedMemorySize, GEMM_SMEM);

    const float s1a = S1_L1, s2a = s1a / 254.0f, s3a = s2a / 254.0f;
    const float s1b = S1_L2, s2b = s1b / 254.0f, s3b = s2b / 254.0f;

    // 1) input spikes -> A1 (int8 [M][NIN])
    {
        dim3 blk(32, 8), grd(T_ / 32, NIN / 32, B_);
        transpose_spike<<<grd, blk>>>(spike, A1);
    }
    // 2) weight 3-term int8 splits
    wsplit_i8<<<(H_ * (NIN / 16) + 255) / 256, 256>>>(W1, W1q, NIN, s1a, s2a, s3a);
    wsplit_i8<<<(H_ * (H_  / 16) + 255) / 256, 256>>>(W2, W2q, H_,  s1b, s2b, s3b);
    // 3) layer-1 GEMM (IMMA)
    {
        dim3 grd(H_ / 64, M_ / 128);
        imma_gemm<<<grd, 512, GEMM_SMEM>>>(A1, W1q, Z, NIN, s1a, s2a, s3a);
    }
    // 4) layer-1 scan -> A2 (int8)
    scan_i8<<<(B_ * H_) / 256, 256>>>(Z, A2);
    // 5) layer-2 GEMM (IMMA)
    {
        dim3 grd(H_ / 64, M_ / 128);
        imma_gemm<<<grd, 512, GEMM_SMEM>>>(A2, W2q, Z, H_, s1b, s2b, s3b);
    }
    // 6) layer-2 scan -> S2 (fp32)
    scan_f32<<<(B_ * H_) / 256, 256>>>(Z, S2, B_ * H_);
    // 7) layer-3
    gemm3_kernel<<<(M_ * 32) / 256, 256>>>(S2, W3, Z3);
    scan3_kernel<<<1, B_ * NOUT>>>(Z3, out);
}

// round 17
// speedup vs baseline: 1.4981x; 1.4981x over previous
#include <cuda_runtime.h>
#include <cuda_fp16.h>
#include <cstdint>

// ---------------- problem dims ----------------
#define B_   64
#define NIN  2048
#define H_   1024
#define NOUT 2
#define T_   128
#define M_   (B_ * T_)          // 8192 time-batched rows

__device__ __constant__ float CD = (float)(1.0 - 0.3);
__device__ __constant__ float VD = (float)(1.0 - 0.8);
#define THRESH 1.0f

// ---------------- scratch ----------------
__device__ uint8_t g_A1[(size_t)M_ * NIN * 2];        // fp16 [M][NIN]
__device__ uint8_t g_A2[(size_t)M_ * H_ * 2];         // fp16 [M][H]
__device__ uint8_t g_W1s[(size_t)2 * H_ * NIN * 2];   // fp16 [sp][H][NIN]
__device__ uint8_t g_W2s[(size_t)2 * H_ * H_ * 2];    // fp16 [sp][H][H]
__device__ float   g_Z [(size_t)M_ * H_];             // fp32 pre-activation
__device__ float   g_S2[(size_t)M_ * H_];             // fp32 layer-2 spikes
__device__ float   g_Z3[(size_t)M_ * NOUT];

// ---------------- PTX helpers (base ISA only) ----------------
__device__ __forceinline__ uint32_t smem_u32(const void* p) {
    uint32_t a;
    asm("{ .reg .u64 t; cvta.to.shared.u64 t, %1; cvt.u32.u64 %0, t; }" : "=r"(a) : "l"(p));
    return a;
}
__device__ __forceinline__ void cpasync16(uint32_t dst, const void* src) {
    asm volatile("cp.async.cg.shared.global [%0], [%1], 16;" :: "r"(dst), "l"(src));
}
#define CP_COMMIT() asm volatile("cp.async.commit_group;" ::: "memory")
#define CP_WAIT1()  asm volatile("cp.async.wait_group 1;" ::: "memory")

__device__ __forceinline__ void ldsm_x4(uint32_t (&r)[4], uint32_t addr) {
    asm volatile("ldmatrix.sync.aligned.m8n8.x4.shared.b16 {%0,%1,%2,%3}, [%4];"
        : "=r"(r[0]), "=r"(r[1]), "=r"(r[2]), "=r"(r[3]) : "r"(addr));
}
__device__ __forceinline__ void mma16816_f32(float (&d)[4], const uint32_t (&a)[4],
                                             uint32_t b0, uint32_t b1) {
    asm volatile(
        "mma.sync.aligned.m16n8k16.row.col.f32.f16.f16.f32 "
        "{%0,%1,%2,%3}, {%4,%5,%6,%7}, {%8,%9}, {%0,%1,%2,%3};"
        : "+f"(d[0]), "+f"(d[1]), "+f"(d[2]), "+f"(d[3])
        : "r"(a[0]), "r"(a[1]), "r"(a[2]), "r"(a[3]), "r"(b0), "r"(b1));
}

// ---------------- 1) transpose + convert: spike [B,I,T] -> A1 fp16 [m=(t*B+b)][i] ----------------
__global__ void transpose_spike(const float* __restrict__ in, __half* __restrict__ a1) {
    __shared__ float tile[32][33];
    const int b  = blockIdx.z;
    const int i0 = blockIdx.y * 32;
    const int t0 = blockIdx.x * 32;
    const int tx = threadIdx.x, ty = threadIdx.y;   // 32 x 8
#pragma unroll
    for (int r = 0; r < 32; r += 8)
        tile[ty + r][tx] = in[((size_t)b * NIN + (i0 + ty + r)) * T_ + (t0 + tx)];
    __syncthreads();
#pragma unroll
    for (int r = 0; r < 32; r += 8) {
        const int t = t0 + ty + r;
        const int i = i0 + tx;
        const int m = t * B_ + b;
        a1[(size_t)m * NIN + i] = __float2half(tile[tx][ty + r]);
    }
}

// ---------------- 2) weight 2-way fp16 split (Dekker) -> [sp][n][K] ----------------
__global__ void wsplit(const float* __restrict__ W, __half* __restrict__ out, int K) {
    const int ng  = K / 8;
    const int idx = blockIdx.x * blockDim.x + threadIdx.x;
    if (idx >= H_ * ng) return;
    const int n = idx / ng, k0 = (idx % ng) * 8;
    union { __half h[8]; uint4 v; } p1, p2;
#pragma unroll
    for (int j = 0; j < 8; j++) {
        float w = W[(size_t)n * K + k0 + j];
        __half h1 = __float2half(w);
        float r1 = w - __half2float(h1);
        __half h2 = __float2half(r1);
        p1.h[j] = h1; p2.h[j] = h2;
    }
    const size_t sz = (size_t)H_ * K;
    *(uint4*)&out[(size_t)0 * sz + (size_t)n * K + k0] = p1.v;
    *(uint4*)&out[(size_t)1 * sz + (size_t)n * K + k0] = p2.v;
}

// ---------------- 3) hybrid GEMM: HMMA CTAs (cols 0..639) + FFMA CTAs (cols 640..1023) ----------------
// HMMA path (R11): CTA 128x128, 8 warps (2x4), K-stage 32, 2-stage cp.async, fp16 2-split.
// FFMA path (R1):  CTA 128x128 SIMT sgemm, BK=16, fp32 exact from original W.
#define NXB   8                        // grid.x: 5 HMMA + 3 FFMA column blocks
#define HXB   5                        // HMMA blocks -> cols [0, 640)
#define ROWB 80                        // 32 fp16 (64B) + 16B pad: ldmatrix conflict-free
#define TILE_BYTES (128 * ROWB)        // 10240
#define STG_BYTES  (3 * TILE_BYTES)    // A + 2 W splits = 30720
#define GEMM_SMEM (2 * STG_BYTES)      // 61440 (HMMA); FFMA uses first 16KB

__device__ __forceinline__ void load_stage(uint32_t st, const uint8_t* __restrict__ Ab,
                                           const uint8_t* __restrict__ Wb,
                                           int bm, int bn, int c, int K, int tid) {
    const size_t krow = (size_t)K * 2;
    const size_t koff = (size_t)c * 64;
#pragma unroll
    for (int i = 0; i < 2; i++) {
        const int idx = i * 256 + tid;
        const int row = idx >> 2, ch = idx & 3;
        cpasync16(st + row * ROWB + ch * 16,
                  Ab + (size_t)(bm + row) * krow + koff + ch * 16);
    }
#pragma unroll
    for (int sp = 0; sp < 2; sp++) {
#pragma unroll
        for (int i = 0; i < 2; i++) {
            const int idx = i * 256 + tid;
            const int row = idx >> 2, ch = idx & 3;
            cpasync16(st + (sp + 1) * TILE_BYTES + row * ROWB + ch * 16,
                      Wb + ((size_t)sp * H_ + bn + row) * krow + koff + ch * 16);
        }
    }
}

__global__ __launch_bounds__(256, 2)
void hyb_gemm(const uint8_t* __restrict__ Ab, const uint8_t* __restrict__ Wb,
              const float* __restrict__ Wf, float* __restrict__ C, int K) {
    extern __shared__ uint8_t smem[];
    const int tid = threadIdx.x;
    const int bm = blockIdx.y * 128;

    if (blockIdx.x < HXB) {
        // ================= HMMA path (identical numerics to R11) =================
        const uint32_t sb = smem_u32(smem);
        const int lane = tid & 31, wid = tid >> 5;
        const int wm = wid >> 2, wn = wid & 3;
        const int bn = blockIdx.x * 128;
        const int nch = K / 32;

        float acc[4][4][4];
#pragma unroll
        for (int i = 0; i < 4; i++)
#pragma unroll
            for (int j = 0; j < 4; j++)
#pragma unroll
                for (int v = 0; v < 4; v++) acc[i][j][v] = 0.f;

        load_stage(sb,             Ab, Wb, bm, bn, 0, K, tid); CP_COMMIT();
        load_stage(sb + STG_BYTES, Ab, Wb, bm, bn, 1, K, tid); CP_COMMIT();

        const int r16  = lane & 15;
        const int hb16 = (lane >> 4) << 4;

        for (int c = 0; c < nch; c++) {
            CP_WAIT1();
            __syncthreads();
            const uint32_t stage = sb + (c & 1) * STG_BYTES;
#pragma unroll
            for (int s = 0; s < 2; s++) {
                uint32_t a[4][4];
#pragma unroll
                for (int i = 0; i < 4; i++)
                    ldsm_x4(a[i], stage + (wm * 64 + i * 16 + r16) * ROWB + s * 32 + hb16);
#pragma unroll
                for (int sp = 0; sp < 2; sp++) {
                    uint32_t b[2][4];
                    const uint32_t bs = stage + (sp + 1) * TILE_BYTES;
#pragma unroll
                    for (int j = 0; j < 2; j++)
                        ldsm_x4(b[j], bs + (wn * 32 + j * 16 + r16) * ROWB + s * 32 + hb16);
#pragma unroll
                    for (int i = 0; i < 4; i++)
#pragma unroll
                        for (int nt = 0; nt < 4; nt++)
                            mma16816_f32(acc[i][nt], a[i],
                                         b[nt >> 1][(nt & 1)], b[nt >> 1][(nt & 1) + 2]);
                }
            }
            __syncthreads();
            if (c + 2 < nch) load_stage(stage, Ab, Wb, bm, bn, c + 2, K, tid);
            CP_COMMIT();
        }

        const int rr = lane >> 2, cc = (lane & 3) * 2;
#pragma unroll
        for (int i = 0; i < 4; i++) {
            const int row = bm + wm * 64 + i * 16 + rr;
#pragma unroll
            for (int nt = 0; nt < 4; nt++) {
                const int col = bn + wn * 32 + nt * 8 + cc;
                *(float2*)&C[(size_t)row * H_ + col] =
                    make_float2(acc[i][nt][0], acc[i][nt][1]);
                *(float2*)&C[(size_t)(row + 8) * H_ + col] =
                    make_float2(acc[i][nt][2], acc[i][nt][3]);
            }
        }
    } else {
        // ================= FFMA path (fp32-exact SIMT sgemm, R1 proven) =================
        float* As = (float*)smem;                 // [16][128]
        float* Bs = As + 16 * 128;                // [16][128]
        const int bn = HXB * 128 + (blockIdx.x - HXB) * 128;
        const int tx = tid & 15, ty = tid >> 4;

        float acc[8][8];
#pragma unroll
        for (int i = 0; i < 8; i++)
#pragma unroll
            for (int j = 0; j < 8; j++) acc[i][j] = 0.f;

        const __half* Ah = (const __half*)Ab;
        for (int k0 = 0; k0 < K; k0 += 16) {
            // A fp16 tile 128x16 = 256 x 8-half segments, convert to fp32 smem
            {
                const int row = tid >> 1, seg = tid & 1;
                union { uint4 v; __half h[8]; } u;
                u.v = *(const uint4*)&Ah[(size_t)(bm + row) * K + k0 + seg * 8];
#pragma unroll
                for (int j = 0; j < 8; j++)
                    As[(seg * 8 + j) * 128 + row] = __half2float(u.h[j]);
            }
            // W fp32 tile 128x16 = 512 float4
#pragma unroll
            for (int l = 0; l < 2; l++) {
                const int v   = tid + l * 256;
                const int row = v >> 2;
                const int c4  = (v & 3) * 4;
                float4 db = *(const float4*)&Wf[((size_t)(bn + row)) * K + k0 + c4];
                Bs[(c4 + 0) * 128 + row] = db.x; Bs[(c4 + 1) * 128 + row] = db.y;
                Bs[(c4 + 2) * 128 + row] = db.z; Bs[(c4 + 3) * 128 + row] = db.w;
            }
            __syncthreads();
#pragma unroll
            for (int k = 0; k < 16; k++) {
                float a[8], b[8];
#pragma unroll
                for (int i = 0; i < 8; i++) a[i] = As[k * 128 + ty * 8 + i];
#pragma unroll
                for (int j = 0; j < 8; j++) b[j] = Bs[k * 128 + tx * 8 + j];
#pragma unroll
                for (int i = 0; i < 8; i++)
#pragma unroll
                    for (int j = 0; j < 8; j++) acc[i][j] += a[i] * b[j];
            }
            __syncthreads();
        }

#pragma unroll
        for (int i = 0; i < 8; i++) {
            const size_t rowoff = ((size_t)(bm + ty * 8 + i)) * H_ + bn + tx * 8;
#pragma unroll
            for (int j = 0; j < 8; j += 4) {
                float4 o = make_float4(acc[i][j], acc[i][j+1], acc[i][j+2], acc[i][j+3]);
                *(float4*)&C[rowoff + j] = o;
            }
        }
    }
}

// ---------------- 4) scans ----------------
__global__ void scan_f16(const float* __restrict__ Z, __half* __restrict__ a2) {
    const int n = blockIdx.x * blockDim.x + threadIdx.x;   // n = b*H + o
    if (n >= B_ * H_) return;
    const int b = n >> 10, o = n & 1023;
    const __half ONE = __float2half(1.0f);
    const __half ZER = __float2half(0.0f);
    float cur = 0.f, vol = 0.f;
    const float cd = CD, vd = VD;
    for (int t = 0; t < T_; t++) {
        const float z = Z[(size_t)t * (B_ * H_) + n];
        cur = cur * cd + z;
        vol = vol * vd + cur;
        const bool s = (vol - THRESH >= 0.f);
        vol = s ? 0.f : vol;
        a2[(size_t)(t * B_ + b) * H_ + o] = s ? ONE : ZER;
    }
}

__global__ void scan_f32(const float* __restrict__ Z, float* __restrict__ S, int Nn) {
    const int n = blockIdx.x * blockDim.x + threadIdx.x;
    if (n >= Nn) return;
    float cur = 0.f, vol = 0.f;
    const float cd = CD, vd = VD;
#pragma unroll 4
    for (int t = 0; t < T_; t++) {
        const float z = Z[(size_t)t * Nn + n];
        cur = cur * cd + z;
        vol = vol * vd + cur;
        const float s = (vol - THRESH >= 0.f) ? 1.f : 0.f;
        vol = (s > 0.f) ? 0.f : vol;
        S[(size_t)t * Nn + n] = s;
    }
}

// ---------------- 5) layer-3 GEMM (N=2): one warp per row ----------------
__global__ void gemm3_kernel(const float* __restrict__ S2, const float* __restrict__ W3,
                             float* __restrict__ Z3) {
    const int warp = (blockIdx.x * blockDim.x + threadIdx.x) >> 5;
    const int lane = threadIdx.x & 31;
    if (warp >= M_) return;
    const float* s = S2 + (size_t)warp * H_;
    float a0 = 0.f, a1 = 0.f;
#pragma unroll 8
    for (int k = lane; k < H_; k += 32) {
        const float sv = s[k];
        a0 += sv * W3[k];
        a1 += sv * W3[H_ + k];
    }
#pragma unroll
    for (int off = 16; off; off >>= 1) {
        a0 += __shfl_xor_sync(0xFFFFFFFFu, a0, off);
        a1 += __shfl_xor_sync(0xFFFFFFFFu, a1, off);
    }
    if (lane == 0) { Z3[(size_t)warp * 2] = a0; Z3[(size_t)warp * 2 + 1] = a1; }
}

// ---------------- 6) layer-3 scan + final output [B, 2, T] ----------------
__global__ void scan3_kernel(const float* __restrict__ Z3, float* __restrict__ out) {
    const int n = threadIdx.x;
    const int b = n >> 1, o = n & 1;
    float cur = 0.f, vol = 0.f;
    const float cd = CD, vd = VD;
    for (int t = 0; t < T_; t++) {
        const float z = Z3[t * (B_ * NOUT) + n];
        cur = cur * cd + z;
        vol = vol * vd + cur;
        const float s = (vol - THRESH >= 0.f) ? 1.f : 0.f;
        vol = (s > 0.f) ? 0.f : vol;
        out[((size_t)b * NOUT + o) * T_ + t] = s;
    }
}

// ---------------- launch ----------------
extern "C" void kernel_launch(void* const* d_in, const int* in_sizes, int n_in,
                              void* d_out, int out_size) {
    const float* spike = (const float*)d_in[0];   // [B, NIN, T]
    const float* W1    = (const float*)d_in[1];   // [H, NIN]
    const float* W2    = (const float*)d_in[2];   // [H, H]
    const float* W3    = (const float*)d_in[3];   // [NOUT, H]
    float* out = (float*)d_out;

    uint8_t *A1, *A2, *W1s, *W2s;
    float *Z, *S2, *Z3;
    cudaGetSymbolAddress((void**)&A1,  g_A1);
    cudaGetSymbolAddress((void**)&A2,  g_A2);
    cudaGetSymbolAddress((void**)&W1s, g_W1s);
    cudaGetSymbolAddress((void**)&W2s, g_W2s);
    cudaGetSymbolAddress((void**)&Z,   g_Z);
    cudaGetSymbolAddress((void**)&S2,  g_S2);
    cudaGetSymbolAddress((void**)&Z3,  g_Z3);

    cudaFuncSetAttribute(hyb_gemm, cudaFuncAttributeMaxDynamicSharedMemorySize, GEMM_SMEM);

    // 1) input spikes -> A1 (fp16 [M][NIN])
    {
        dim3 blk(32, 8), grd(T_ / 32, NIN / 32, B_);
        transpose_spike<<<grd, blk>>>(spike, (__half*)A1);
    }
    // 2) weight splits (fp16 Dekker 2-way, for the HMMA columns)
    wsplit<<<(H_ * (NIN / 8) + 255) / 256, 256>>>(W1, (__half*)W1s, NIN);
    wsplit<<<(H_ * (H_  / 8) + 255) / 256, 256>>>(W2, (__half*)W2s, H_);
    // 3) layer-1 hybrid GEMM (tensor + fma pipes concurrently)
    {
        dim3 grd(NXB, M_ / 128);
        hyb_gemm<<<grd, 256, GEMM_SMEM>>>(A1, W1s, W1, Z, NIN);
    }
    // 4) layer-1 scan -> A2 (fp16)
    scan_f16<<<(B_ * H_) / 256, 256>>>(Z, (__half*)A2);
    // 5) layer-2 hybrid GEMM
    {
        dim3 grd(NXB, M_ / 128);
        hyb_gemm<<<grd, 256, GEMM_SMEM>>>(A2, W2s, W2, Z, H_);
    }
    // 6) layer-2 scan -> S2 (fp32)
    scan_f32<<<(B_ * H_) / 256, 256>>>(Z, S2, B_ * H_);
    // 7) layer-3
    gemm3_kernel<<<(M_ * 32) / 256, 256>>>(S2, W3, Z3);
    scan3_kernel<<<1, B_ * NOUT>>>(Z3, out);
}